// round 16
// baseline (speedup 1.0000x reference)
#include <cuda_runtime.h>

// Problem shapes (fixed for this dataset entry)
#define B_   4
#define Q_   128
#define N_   50000
#define C_   20
#define BQ_  (B_ * Q_)          // 512
#define BN_  (B_ * N_)          // 200000
#define NV_  (N_ / 4)           // 12500 float4 per row
#define S_   10                 // producer chunks per row
#define CHUNK_ (NV_ / S_)       // 1250 float4 per chunk
#define NSTREAM_ 250            // threads 0..249 stream 5 float4 each (=1250)
#define NPROD_ (BQ_ * S_)       // 5120 producer blocks
#define NEPI_  2                // 2 epilogue blocks (512 threads = 512 rows)
#define GIDV_ (BN_ / 4)         // 50000 int4 for gid convert

#define MIN_PTS_NUM  50
#define MIN_INST_CLS 4
#define FIXSCALE 16777216.0f    // 2^24 fixed-point (deterministic u64 sum)

// Output layout (fp32 concatenation, matching reference return order)
#define OFF_SCORES ((size_t)BQ_ * N_)            // 25,600,000
#define OFF_VALID  (OFF_SCORES + BQ_)
#define OFF_CLS    (OFF_VALID + BQ_)
#define OFF_GID    (OFF_CLS + BQ_)

// Scratch (no device allocation -> __device__ globals). Accumulated via
// relaxed atomics within a launch; the epilogue thread of each row reads the
// totals (after all 10 arrivals) and resets them -> initial state restored
// every invocation (graph-replay safe; integer atomics order-independent ->
// deterministic).
__device__ int                g_cnt_tot[BQ_];
__device__ unsigned long long g_sum_tot[BQ_];
__device__ unsigned int       g_arrive[BQ_];

// Inline per-row argmax over C=20 class logits. Matches jnp.argmax first-max.
__device__ __forceinline__ int row_argmax(const float* __restrict__ p)
{
    float best = __ldg(&p[0]);
    int bi = 0;
    #pragma unroll
    for (int c = 1; c < C_; c++) {
        float v = __ldg(&p[c]);
        if (v > best) { best = v; bi = c; }
    }
    return bi;
}

// ---------------------------------------------------------------------------
// Single launch, flat grid of NEPI_+NPROD_ = 5122 blocks.
//
//  Blocks 0..1 (epilogue): FIRST convert the whole gid array (1.6 MB) in an
//    unrolled grid-stride loop -- useful work fully overlapped with the
//    producer phase (these blocks would otherwise idle ~30 us). Then thread
//    t spins (acquire + nanosleep) on row bq = blockIdx.x*256+t until its 10
//    producers arrive, reads totals, argmax, writes score/valid/cls, resets
//    counters. Early rows' epilogues overlap later producers; only the
//    straggler tail is exposed. 2/888 resident slots stolen (R13's 512
//    spinner blocks were the regression mechanism; 2 is noise).
//
//  Blocks 2..5121 (producers): exactly the R7-shaped streaming block -- no
//    gid branch, no int count chain. One 1250-float4 chunk of row bq;
//    threads 0..249 stream 5 float4 each (no bounds predicates);
//    sel = (logit>0)&(seg==cls) [sigmoid(x)>0.5 <=> x>0, no MUFU for
//    select]; count accumulated as float from the already-computed 0/1 mask
//    values (exact, associative -> deterministic); sigmoid only on selected
//    (~2.5%). Thread 250 (issues NO mask stores) publishes totals as relaxed
//    atomics then fire-and-forget red.release.gpu -- drains only its own
//    ATOMGs, never the block's store queue, no result dependency.
// ---------------------------------------------------------------------------
__global__ __launch_bounds__(256, 6)
void fused_kernel(const float* __restrict__ mask_logits,
                  const float* __restrict__ cls_logits,
                  const int* __restrict__ seg_pred,
                  const int* __restrict__ fg_idxs,
                  float* __restrict__ out_masks,
                  float* __restrict__ out_scores,
                  float* __restrict__ out_valid,
                  float* __restrict__ out_cls,
                  float* __restrict__ out_gid)
{
    const int tid = threadIdx.x;

    if (blockIdx.x < NEPI_) {
        // -------- epilogue blocks: gid convert first (overlapped) --------
        {
            const int4*  __restrict__ gv = reinterpret_cast<const int4*>(fg_idxs);
            float4*      __restrict__ go = reinterpret_cast<float4*>(out_gid);
            int start = blockIdx.x * 256 + tid;       // 0..511
            #pragma unroll 4
            for (int vi = start; vi < GIDV_; vi += NEPI_ * 256) {
                int4 g = __ldg(&gv[vi]);
                float4 f;
                f.x = (float)g.x; f.y = (float)g.y;
                f.z = (float)g.z; f.w = (float)g.w;
                go[vi] = f;
            }
        }

        // -------- per-row epilogue: one thread per row --------
        const int bq = blockIdx.x * 256 + tid;        // 0..511
        unsigned int v;
        const unsigned int* ap = &g_arrive[bq];
        do {
            asm volatile("ld.acquire.gpu.global.u32 %0, [%1];"
                         : "=r"(v) : "l"(ap));
            if (v < S_) __nanosleep(256);
        } while (v < S_);

        int                cnt = __ldcg(&g_cnt_tot[bq]);
        unsigned long long fs  = __ldcg(&g_sum_tot[bq]);
        const int cls = row_argmax(cls_logits + bq * C_);
        const int val = (cnt >= MIN_PTS_NUM) && (cls >= MIN_INST_CLS);
        out_cls[bq]    = (float)cls;
        out_valid[bq]  = (float)val;
        float sum = (float)((double)fs * (1.0 / 16777216.0));
        out_scores[bq] = val ? sum / (float)cnt : 0.f;
        // Reset for next replay (all producers arrived -> race-free).
        g_cnt_tot[bq] = 0;
        g_sum_tot[bq] = 0ULL;
        g_arrive[bq]  = 0u;

        // Never-taken safety net (cnt~1250 >> 50 for instance classes).
        if (!val && cls >= MIN_INST_CLS) {
            float4* __restrict__ zm = reinterpret_cast<float4*>(out_masks) +
                                      (size_t)bq * NV_;
            const float4 z = make_float4(0.f, 0.f, 0.f, 0.f);
            for (int i = 0; i < NV_; i++) __stcs(&zm[i], z);
        }
        return;
    }

    // ---------------- producer block (R7-shaped) ----------------
    const int fb    = blockIdx.x - NEPI_;             // 0..5119
    const int bq    = fb / S_;
    const int chunk = fb - bq * S_;
    const int b     = bq >> 7;                        // / Q_
    const int cls   = row_argmax(cls_logits + bq * C_);
    const size_t base = (size_t)bq * NV_ + (size_t)chunk * CHUNK_;

    float4* __restrict__ om = reinterpret_cast<float4*>(out_masks) + base;

    float fcnt = 0.f;
    float ssum = 0.f;

    if (cls < MIN_INST_CLS) {
        const float4 z = make_float4(0.f, 0.f, 0.f, 0.f);
        if (tid < NSTREAM_) {
            #pragma unroll
            for (int k = 0; k < 5; k++)
                __stcs(&om[tid + k * NSTREAM_], z);
        }
    } else if (tid < NSTREAM_) {
        const float4* __restrict__ ml = reinterpret_cast<const float4*>(mask_logits) + base;
        const int4*   __restrict__ sp = reinterpret_cast<const int4*>(seg_pred) +
                                        (size_t)b * NV_ + (size_t)chunk * CHUNK_;

        // 5 (float4, int4) pairs, front-batched for MLP, no predicates.
        float4 x[5]; int4 s[5];
        #pragma unroll
        for (int k = 0; k < 5; k++) {
            int i = tid + k * NSTREAM_;
            x[k] = __ldcs(&ml[i]);
            s[k] = __ldg(&sp[i]);
        }
        #pragma unroll
        for (int k = 0; k < 5; k++) {
            int i = tid + k * NSTREAM_;
            bool s0 = (x[k].x > 0.f) & (s[k].x == cls);
            bool s1 = (x[k].y > 0.f) & (s[k].y == cls);
            bool s2 = (x[k].z > 0.f) & (s[k].z == cls);
            bool s3 = (x[k].w > 0.f) & (s[k].w == cls);
            float4 o;
            o.x = s0 ? 1.f : 0.f;
            o.y = s1 ? 1.f : 0.f;
            o.z = s2 ? 1.f : 0.f;
            o.w = s3 ? 1.f : 0.f;
            __stcs(&om[i], o);
            fcnt += (o.x + o.y) + (o.z + o.w);        // exact 0/1 sums
            if (s0 | s1 | s2 | s3) {
                if (s0) ssum += __fdividef(1.f, 1.f + __expf(-x[k].x));
                if (s1) ssum += __fdividef(1.f, 1.f + __expf(-x[k].y));
                if (s2) ssum += __fdividef(1.f, 1.f + __expf(-x[k].z));
                if (s3) ssum += __fdividef(1.f, 1.f + __expf(-x[k].w));
            }
        }
    }

    // Fixed-point conversion before reduction (both exact/deterministic).
    unsigned long long fsum = (unsigned long long)(ssum * FIXSCALE + 0.5f);
    int                icnt = (int)fcnt;              // exact integer

    // Block reduction (8 warps); fixed tree -> deterministic.
    __shared__ int                scnt[8];
    __shared__ unsigned long long ssh[8];
    #pragma unroll
    for (int off = 16; off > 0; off >>= 1) {
        icnt += __shfl_down_sync(0xFFFFFFFFu, icnt, off);
        fsum += __shfl_down_sync(0xFFFFFFFFu, fsum, off);
    }
    int wid  = tid >> 5;
    int lane = tid & 31;
    if (lane == 0) { scnt[wid] = icnt; ssh[wid] = fsum; }
    __syncthreads();

    // Thread 250 (no mask stores in its queue): publish + release-arrive,
    // no result dependency -> block retires immediately.
    if (tid == NSTREAM_) {
        if (cls >= MIN_INST_CLS) {
            int tc = 0; unsigned long long ts = 0ULL;
            #pragma unroll
            for (int w = 0; w < 8; w++) { tc += scnt[w]; ts += ssh[w]; }
            if (tc > 0) {
                atomicAdd(&g_cnt_tot[bq], tc);        // relaxed, L2-resident
                atomicAdd(&g_sum_tot[bq], ts);
            }
        }
        asm volatile("red.release.gpu.global.add.u32 [%0], %1;"
                     :: "l"(&g_arrive[bq]), "r"(1u) : "memory");
    }
}

// ---------------------------------------------------------------------------
extern "C" void kernel_launch(void* const* d_in, const int* in_sizes, int n_in,
                              void* d_out, int out_size)
{
    const float* mask_logits = (const float*)d_in[0];   // [B,Q,N]  fp32
    const float* cls_logits  = (const float*)d_in[1];   // [B,Q,C]  fp32
    const int*   seg_pred    = (const int*)d_in[2];     // [B,N]    int32
    const int*   fg_idxs     = (const int*)d_in[3];     // [B*N]    int32
    float* out = (float*)d_out;

    float* out_masks  = out;
    float* out_scores = out + OFF_SCORES;
    float* out_valid  = out + OFF_VALID;
    float* out_cls    = out + OFF_CLS;
    float* out_gid    = out + OFF_GID;

    fused_kernel<<<NEPI_ + NPROD_, 256>>>(mask_logits, cls_logits, seg_pred,
                                          fg_idxs, out_masks, out_scores,
                                          out_valid, out_cls, out_gid);
}

// round 17
// speedup vs baseline: 1.0357x; 1.0357x over previous
#include <cuda_runtime.h>

// Problem shapes (fixed for this dataset entry)
#define B_   4
#define Q_   128
#define N_   50000
#define C_   20
#define BQ_  (B_ * Q_)          // 512
#define BN_  (B_ * N_)          // 200000
#define NV_  (N_ / 4)           // 12500 float4 per row
#define S_   10                 // producer chunks per row
#define CHUNK_ (NV_ / S_)       // 1250 float4 per chunk
#define NPROD_ (BQ_ * S_)       // 5120 producer blocks
#define NEPI_  2                // 2 epilogue blocks (512 threads = 512 rows)
#define GIDV_ (BN_ / 4)         // 50000 int4 for gid convert

#define MIN_PTS_NUM  50
#define MIN_INST_CLS 4
#define FIXSCALE 16777216.0f    // 2^24 fixed-point (deterministic u64 sum)

// Packed-u64 protocol: [arrive:4 | cnt:18 | fixsum:42]
#define PACK_ARRIVE_SHIFT 60
#define PACK_CNT_SHIFT    42
#define PACK_SUM_MASK     ((1ULL << 42) - 1ULL)
#define PACK_CNT_MASK     ((1ULL << 18) - 1ULL)

// Output layout (fp32 concatenation, matching reference return order)
#define OFF_SCORES ((size_t)BQ_ * N_)            // 25,600,000
#define OFF_VALID  (OFF_SCORES + BQ_)
#define OFF_CLS    (OFF_VALID + BQ_)
#define OFF_GID    (OFF_CLS + BQ_)

// Scratch (no device allocation -> __device__ globals). One packed u64 per
// row: producers atomicAdd (relaxed) arrival+count+sum in a single word ->
// when arrive==10 the data is complete BY CONSTRUCTION (same address), so no
// release/acquire/fence anywhere. Epilogue resets to 0 after reading ->
// initial state restored every invocation (graph-replay safe; integer adds
// order-independent -> deterministic).
__device__ unsigned long long g_row_acc[BQ_];

// Inline per-row argmax over C=20 class logits. Matches jnp.argmax first-max.
__device__ __forceinline__ int row_argmax(const float* __restrict__ p)
{
    float best = __ldg(&p[0]);
    int bi = 0;
    #pragma unroll
    for (int c = 1; c < C_; c++) {
        float v = __ldg(&p[c]);
        if (v > best) { best = v; bi = c; }
    }
    return bi;
}

// ---------------------------------------------------------------------------
// Single launch, flat grid of NEPI_+NPROD_ = 5122 blocks.
//
//  Blocks 0..1 (epilogue): first convert the gid array (1.6 MB, grid-stride)
//    -- overlapped with the producer phase. Then thread t owns row
//    bq = blockIdx.x*256+t: spin (relaxed u64 load + nanosleep) until the
//    packed word shows 10 arrivals; count+sum ride in the SAME word, so no
//    memory-ordering instructions are needed at all. Write score/valid/cls,
//    reset the word.
//
//  Blocks 2..5121 (producers): R7's exact streaming shape (measured-best):
//    256 threads, 5 float4 each, stride 256, last iteration predicated.
//    sel = (logit>0)&(seg==cls) [sigmoid(x)>0.5 <=> x>0, no MUFU for
//    select]; sigmoid only on selected (~2.5%). Block-reduce, then thread 0
//    issues ONE relaxed u64 atomicAdd carrying arrival+count+sum.
//    Field bounds: sum <= 10*5000*2^24 ~ 8.4e11 < 2^42; cnt <= 50000 < 2^18;
//    no cross-field carries possible.
// ---------------------------------------------------------------------------
__global__ __launch_bounds__(256, 6)
void fused_kernel(const float* __restrict__ mask_logits,
                  const float* __restrict__ cls_logits,
                  const int* __restrict__ seg_pred,
                  const int* __restrict__ fg_idxs,
                  float* __restrict__ out_masks,
                  float* __restrict__ out_scores,
                  float* __restrict__ out_valid,
                  float* __restrict__ out_cls,
                  float* __restrict__ out_gid)
{
    const int tid = threadIdx.x;

    if (blockIdx.x < NEPI_) {
        // -------- epilogue blocks: gid convert first (overlapped) --------
        {
            const int4* __restrict__ gv = reinterpret_cast<const int4*>(fg_idxs);
            float4*     __restrict__ go = reinterpret_cast<float4*>(out_gid);
            int start = blockIdx.x * 256 + tid;       // 0..511
            #pragma unroll 4
            for (int vi = start; vi < GIDV_; vi += NEPI_ * 256) {
                int4 g = __ldg(&gv[vi]);
                float4 f;
                f.x = (float)g.x; f.y = (float)g.y;
                f.z = (float)g.z; f.w = (float)g.w;
                go[vi] = f;
            }
        }

        // -------- per-row epilogue: one thread per row --------
        const int bq = blockIdx.x * 256 + tid;        // 0..511
        unsigned long long acc;
        const unsigned long long* ap = &g_row_acc[bq];
        do {
            asm volatile("ld.relaxed.gpu.global.u64 %0, [%1];"
                         : "=l"(acc) : "l"(ap));
            if ((acc >> PACK_ARRIVE_SHIFT) < S_) __nanosleep(256);
        } while ((acc >> PACK_ARRIVE_SHIFT) < S_);

        const int                cnt = (int)((acc >> PACK_CNT_SHIFT) & PACK_CNT_MASK);
        const unsigned long long fs  = acc & PACK_SUM_MASK;
        const int cls = row_argmax(cls_logits + bq * C_);
        const int val = (cnt >= MIN_PTS_NUM) && (cls >= MIN_INST_CLS);
        out_cls[bq]    = (float)cls;
        out_valid[bq]  = (float)val;
        float sum = (float)((double)fs * (1.0 / 16777216.0));
        out_scores[bq] = val ? sum / (float)cnt : 0.f;
        g_row_acc[bq] = 0ULL;             // reset for next replay (race-free)

        // Never-taken safety net (cnt~1250 >> 50 for instance classes).
        if (!val && cls >= MIN_INST_CLS) {
            float4* __restrict__ zm = reinterpret_cast<float4*>(out_masks) +
                                      (size_t)bq * NV_;
            const float4 z = make_float4(0.f, 0.f, 0.f, 0.f);
            for (int i = 0; i < NV_; i++) __stcs(&zm[i], z);
        }
        return;
    }

    // ---------------- producer block (R7-exact streaming) ----------------
    const int fb    = blockIdx.x - NEPI_;             // 0..5119
    const int bq    = fb / S_;
    const int chunk = fb - bq * S_;
    const int b     = bq >> 7;                        // / Q_
    const int cls   = row_argmax(cls_logits + bq * C_);
    const size_t base = (size_t)bq * NV_ + (size_t)chunk * CHUNK_;

    float4* __restrict__ om = reinterpret_cast<float4*>(out_masks) + base;

    int   cnt  = 0;
    float ssum = 0.f;

    if (cls < MIN_INST_CLS) {
        const float4 z = make_float4(0.f, 0.f, 0.f, 0.f);
        #pragma unroll
        for (int k = 0; k < 5; k++) {
            int i = tid + k * 256;
            if (i < CHUNK_) __stcs(&om[i], z);
        }
    } else {
        const float4* __restrict__ ml = reinterpret_cast<const float4*>(mask_logits) + base;
        const int4*   __restrict__ sp = reinterpret_cast<const int4*>(seg_pred) +
                                        (size_t)b * NV_ + (size_t)chunk * CHUNK_;

        // 5 (float4, int4) pairs; k<4 bounds compile-time true (1024<1250).
        float4 x[5]; int4 s[5];
        #pragma unroll
        for (int k = 0; k < 5; k++) {
            int i = tid + k * 256;
            if (k < 4 || i < CHUNK_) { x[k] = __ldcs(&ml[i]); s[k] = __ldg(&sp[i]); }
        }
        #pragma unroll
        for (int k = 0; k < 5; k++) {
            int i = tid + k * 256;
            if (k == 4 && i >= CHUNK_) continue;
            bool s0 = (x[k].x > 0.f) & (s[k].x == cls);
            bool s1 = (x[k].y > 0.f) & (s[k].y == cls);
            bool s2 = (x[k].z > 0.f) & (s[k].z == cls);
            bool s3 = (x[k].w > 0.f) & (s[k].w == cls);
            float4 o;
            o.x = s0 ? 1.f : 0.f;
            o.y = s1 ? 1.f : 0.f;
            o.z = s2 ? 1.f : 0.f;
            o.w = s3 ? 1.f : 0.f;
            __stcs(&om[i], o);
            cnt += (int)s0 + (int)s1 + (int)s2 + (int)s3;
            if (s0 | s1 | s2 | s3) {
                if (s0) ssum += __fdividef(1.f, 1.f + __expf(-x[k].x));
                if (s1) ssum += __fdividef(1.f, 1.f + __expf(-x[k].y));
                if (s2) ssum += __fdividef(1.f, 1.f + __expf(-x[k].z));
                if (s3) ssum += __fdividef(1.f, 1.f + __expf(-x[k].w));
            }
        }
    }

    // Deterministic fixed-point conversion before reduction.
    unsigned long long fsum = (unsigned long long)(ssum * FIXSCALE + 0.5f);

    // Block reduction (8 warps); fixed tree -> deterministic.
    __shared__ int                scnt[8];
    __shared__ unsigned long long ssh[8];
    #pragma unroll
    for (int off = 16; off > 0; off >>= 1) {
        cnt  += __shfl_down_sync(0xFFFFFFFFu, cnt,  off);
        fsum += __shfl_down_sync(0xFFFFFFFFu, fsum, off);
    }
    int wid  = tid >> 5;
    int lane = tid & 31;
    if (lane == 0) { scnt[wid] = cnt; ssh[wid] = fsum; }
    __syncthreads();

    // ONE relaxed u64 atomic carries arrival + count + sum together.
    if (tid == 0) {
        int tc = 0; unsigned long long ts = 0ULL;
        #pragma unroll
        for (int w = 0; w < 8; w++) { tc += scnt[w]; ts += ssh[w]; }
        unsigned long long pkt = (1ULL << PACK_ARRIVE_SHIFT)
                               | ((unsigned long long)tc << PACK_CNT_SHIFT)
                               | ts;
        atomicAdd(&g_row_acc[bq], pkt);   // relaxed; no ordering needed
    }
}

// ---------------------------------------------------------------------------
extern "C" void kernel_launch(void* const* d_in, const int* in_sizes, int n_in,
                              void* d_out, int out_size)
{
    const float* mask_logits = (const float*)d_in[0];   // [B,Q,N]  fp32
    const float* cls_logits  = (const float*)d_in[1];   // [B,Q,C]  fp32
    const int*   seg_pred    = (const int*)d_in[2];     // [B,N]    int32
    const int*   fg_idxs     = (const int*)d_in[3];     // [B*N]    int32
    float* out = (float*)d_out;

    float* out_masks  = out;
    float* out_scores = out + OFF_SCORES;
    float* out_valid  = out + OFF_VALID;
    float* out_cls    = out + OFF_CLS;
    float* out_gid    = out + OFF_GID;

    fused_kernel<<<NEPI_ + NPROD_, 256>>>(mask_logits, cls_logits, seg_pred,
                                          fg_idxs, out_masks, out_scores,
                                          out_valid, out_cls, out_gid);
}